// round 8
// baseline (speedup 1.0000x reference)
#include <cuda_runtime.h>
#include <cstdint>

#define D_MODEL 1024
#define NHEAD   16
#define DK      64
#define BB      2
#define SEQ     2048
#define MROWS   (BB * SEQ)   // 4096
#define NBH     (BB * NHEAD) // 32

// attention tiling
#define QROWS 64
#define CHUNK 128
#define NCH   (SEQ / CHUNK)  // 16

// padded smem strides (u32 units)
#define KSTR  68             // K chunk [128 keys][64 d]   (key-major)
#define VSTR  132            // V chunk [64 d][128 keys]   (d-major)
#define QSTR  68             // Q tile  [64 rows][64 d]
#define PPAD  36             // per-warp P patch [16 rows][32 keys]
#define KBUF  (128 * KSTR)   // 8704
#define VBUF  (64 * VSTR)    // 8448

// projection GEMM strides
#define ASTR  20
#define BSTR  136

// ---------------- scratch (device globals) -----------------------------------
__device__ uint32_t g_qin[MROWS * D_MODEL];
__device__ uint32_t g_kin[MROWS * D_MODEL];
__device__ uint32_t g_vin[MROWS * D_MODEL];
__device__ uint32_t g_wqc[D_MODEL * D_MODEL];
__device__ uint32_t g_wkc[D_MODEL * D_MODEL];
__device__ uint32_t g_wvc[D_MODEL * D_MODEL];
__device__ uint32_t g_woc[D_MODEL * D_MODEL];
__device__ uint32_t g_qh [NBH * SEQ * DK];   // [bh][s][d] tf32, pre-scaled 1/8
__device__ uint32_t g_kh [NBH * SEQ * DK];   // [bh][s][d] tf32 (key-major)
__device__ uint32_t g_vT [NBH * DK * SEQ];   // [bh][d][s] tf32 (transposed)
__device__ uint32_t g_ctx[MROWS * D_MODEL];  // [b*S+s][h*64+d] tf32

// ---------------- helpers ----------------------------------------------------
__device__ __forceinline__ uint32_t f2tf(float x) {
    uint32_t u;
    asm("cvt.rna.tf32.f32 %0, %1;" : "=r"(u) : "f"(x));
    return u;
}

__device__ __forceinline__ void mma8(float* d, const uint32_t* a,
                                     uint32_t b0, uint32_t b1) {
    asm volatile(
        "mma.sync.aligned.m16n8k8.row.col.f32.tf32.tf32.f32 "
        "{%0,%1,%2,%3}, {%4,%5,%6,%7}, {%8,%9}, {%0,%1,%2,%3};"
        : "+f"(d[0]), "+f"(d[1]), "+f"(d[2]), "+f"(d[3])
        : "r"(a[0]), "r"(a[1]), "r"(a[2]), "r"(a[3]), "r"(b0), "r"(b1));
}

__device__ __forceinline__ void ldsm4(uint32_t* r, uint32_t saddr) {
    asm volatile(
        "ldmatrix.sync.aligned.m8n8.x4.shared.b16 {%0,%1,%2,%3}, [%4];"
        : "=r"(r[0]), "=r"(r[1]), "=r"(r[2]), "=r"(r[3]) : "r"(saddr));
}

__device__ __forceinline__ void cpa16(uint32_t dst, const void* src) {
    asm volatile("cp.async.cg.shared.global [%0], [%1], 16;"
                 :: "r"(dst), "l"(src) : "memory");
}
#define CPA_COMMIT() asm volatile("cp.async.commit_group;" ::: "memory")
#define CPA_WAIT1()  asm volatile("cp.async.wait_group 1;" ::: "memory")
#define CPA_WAIT0()  asm volatile("cp.async.wait_group 0;" ::: "memory")

// ---------------- pre-convert fp32 -> tf32 bits -------------------------------
__global__ void __launch_bounds__(256) cvt_inputs(
    const float* __restrict__ q, const float* __restrict__ k,
    const float* __restrict__ v)
{
    const float* src = (blockIdx.y == 0) ? q : (blockIdx.y == 1) ? k : v;
    uint32_t* dst = (blockIdx.y == 0) ? g_qin : (blockIdx.y == 1) ? g_kin : g_vin;
    const int i = (blockIdx.x * 256 + threadIdx.x) * 4;
    float4 f = *(const float4*)&src[i];
    uint4 o;
    o.x = f2tf(f.x); o.y = f2tf(f.y); o.z = f2tf(f.z); o.w = f2tf(f.w);
    *(uint4*)&dst[i] = o;
}

__global__ void __launch_bounds__(256) cvt_weights(
    const float* __restrict__ wq, const float* __restrict__ wk,
    const float* __restrict__ wv, const float* __restrict__ wo)
{
    const float* src = (blockIdx.y == 0) ? wq : (blockIdx.y == 1) ? wk
                     : (blockIdx.y == 2) ? wv : wo;
    uint32_t* dst = (blockIdx.y == 0) ? g_wqc : (blockIdx.y == 1) ? g_wkc
                  : (blockIdx.y == 2) ? g_wvc : g_woc;
    const int i = (blockIdx.x * 256 + threadIdx.x) * 4;
    float4 f = *(const float4*)&src[i];
    uint4 o;
    o.x = f2tf(f.x); o.y = f2tf(f.y); o.z = f2tf(f.z); o.w = f2tf(f.w);
    *(uint4*)&dst[i] = o;
}

// ---------------- tf32 tensor GEMM (unchanged) -------------------------------
__device__ __forceinline__ void gemm_tf32(
    const uint32_t* __restrict__ A, const uint32_t* __restrict__ W,
    const float* __restrict__ bias, void* __restrict__ outp,
    int mode, uint32_t* As, uint32_t* Bs)
{
    const int t    = threadIdx.x;
    const int lane = t & 31;
    const int w    = t >> 5;
    const int g    = lane >> 2;
    const int t4   = lane & 3;
    const int bm   = blockIdx.y * 128;
    const int bn   = blockIdx.x * 128;
    const int wm   = (w >> 1) * 32;
    const int wn   = (w & 1) * 64;

    const int a_m = t >> 1, a_c = (t & 1) * 8;
    const int w_k = t >> 4, w_c = (t & 15) * 8;

    const uint32_t* aptr = A + (size_t)(bm + a_m) * 1024 + a_c;
    const uint32_t* wptr = W + (size_t)w_k * 1024 + bn + w_c;

    float acc[2][8][4];
#pragma unroll
    for (int mt = 0; mt < 2; ++mt)
#pragma unroll
        for (int nt = 0; nt < 8; ++nt)
#pragma unroll
            for (int i = 0; i < 4; ++i) acc[mt][nt][i] = 0.f;

    uint4 ra0, ra1, rb0, rb1;

    ra0 = *(const uint4*)(aptr);
    ra1 = *(const uint4*)(aptr + 4);
    rb0 = *(const uint4*)(wptr);
    rb1 = *(const uint4*)(wptr + 4);
    *(uint4*)&As[a_m * ASTR + a_c]     = ra0;
    *(uint4*)&As[a_m * ASTR + a_c + 4] = ra1;
    *(uint4*)&Bs[w_k * BSTR + w_c]     = rb0;
    *(uint4*)&Bs[w_k * BSTR + w_c + 4] = rb1;
    __syncthreads();

    for (int it = 0; it < 64; ++it) {
        const int buf = it & 1;
        if (it < 63) {
            const int k0 = (it + 1) * 16;
            ra0 = *(const uint4*)(aptr + k0);
            ra1 = *(const uint4*)(aptr + k0 + 4);
            rb0 = *(const uint4*)(wptr + (size_t)k0 * 1024);
            rb1 = *(const uint4*)(wptr + (size_t)k0 * 1024 + 4);
        }
        const uint32_t* Ab = As + buf * (128 * ASTR);
        const uint32_t* Bb = Bs + buf * (16 * BSTR);
#pragma unroll
        for (int ks = 0; ks < 2; ++ks) {
            uint32_t af[2][4];
#pragma unroll
            for (int mt = 0; mt < 2; ++mt) {
                const int r0 = wm + mt * 16 + g;
                af[mt][0] = Ab[r0       * ASTR + ks * 8 + t4];
                af[mt][1] = Ab[(r0 + 8) * ASTR + ks * 8 + t4];
                af[mt][2] = Ab[r0       * ASTR + ks * 8 + t4 + 4];
                af[mt][3] = Ab[(r0 + 8) * ASTR + ks * 8 + t4 + 4];
            }
#pragma unroll
            for (int nt = 0; nt < 8; ++nt) {
                const int nc = wn + nt * 8 + g;
                uint32_t b0 = Bb[(ks * 8 + t4)     * BSTR + nc];
                uint32_t b1 = Bb[(ks * 8 + t4 + 4) * BSTR + nc];
                mma8(acc[0][nt], af[0], b0, b1);
                mma8(acc[1][nt], af[1], b0, b1);
            }
        }
        if (it < 63) {
            uint32_t* a_s = As + (buf ^ 1) * (128 * ASTR) + a_m * ASTR + a_c;
            *(uint4*)(a_s)     = ra0;
            *(uint4*)(a_s + 4) = ra1;
            uint32_t* b_s = Bs + (buf ^ 1) * (16 * BSTR) + w_k * BSTR + w_c;
            *(uint4*)(b_s)     = rb0;
            *(uint4*)(b_s + 4) = rb1;
        }
        __syncthreads();
    }

#pragma unroll
    for (int mt = 0; mt < 2; ++mt) {
        const int m0 = bm + wm + mt * 16 + g;
#pragma unroll
        for (int nt = 0; nt < 8; ++nt) {
            const int n0 = bn + wn + nt * 8 + 2 * t4;
            const float bz0 = bias[n0], bz1 = bias[n0 + 1];
            float v00 = acc[mt][nt][0] + bz0;
            float v01 = acc[mt][nt][1] + bz1;
            float v10 = acc[mt][nt][2] + bz0;
            float v11 = acc[mt][nt][3] + bz1;
            if (mode == 0) {
                float* out = (float*)outp;
                *(float2*)&out[(size_t)m0 * 1024 + n0]       = make_float2(v00, v01);
                *(float2*)&out[(size_t)(m0 + 8) * 1024 + n0] = make_float2(v10, v11);
            } else {
                uint32_t* out = (uint32_t*)outp;
                const int b0i = m0 >> 11, s0 = m0 & 2047;
                const int h = n0 >> 6, d = n0 & 63;
                const int bh = b0i * NHEAD + h;
                if (mode == 1) {
                    *(uint2*)&out[((size_t)bh * SEQ + s0) * DK + d] =
                        make_uint2(f2tf(v00 * 0.125f), f2tf(v01 * 0.125f));
                    *(uint2*)&out[((size_t)bh * SEQ + s0 + 8) * DK + d] =
                        make_uint2(f2tf(v10 * 0.125f), f2tf(v11 * 0.125f));
                } else if (mode == 3) {
                    *(uint2*)&out[((size_t)bh * SEQ + s0) * DK + d] =
                        make_uint2(f2tf(v00), f2tf(v01));
                    *(uint2*)&out[((size_t)bh * SEQ + s0 + 8) * DK + d] =
                        make_uint2(f2tf(v10), f2tf(v11));
                } else { // mode 2: transposed [bh][d][s]
                    uint32_t* ob = out + (size_t)bh * DK * SEQ;
                    ob[(size_t)d       * SEQ + s0]     = f2tf(v00);
                    ob[(size_t)(d + 1) * SEQ + s0]     = f2tf(v01);
                    ob[(size_t)d       * SEQ + s0 + 8] = f2tf(v10);
                    ob[(size_t)(d + 1) * SEQ + s0 + 8] = f2tf(v11);
                }
            }
        }
    }
}

__global__ void __launch_bounds__(256) qkv_gemm_p(
    const float* __restrict__ bq, const float* __restrict__ bk,
    const float* __restrict__ bv)
{
    __shared__ uint32_t As[2 * 128 * ASTR];
    __shared__ uint32_t Bs[2 * 16 * BSTR];
    const int z = blockIdx.z;
    const uint32_t* A    = (z == 0) ? g_qin : (z == 1) ? g_kin : g_vin;
    const uint32_t* W    = (z == 0) ? g_wqc : (z == 1) ? g_wkc : g_wvc;
    const float*    bias = (z == 0) ? bq    : (z == 1) ? bk    : bv;
    uint32_t* out        = (z == 0) ? g_qh  : (z == 1) ? g_kh  : g_vT;
    const int mode       = (z == 0) ? 1     : (z == 1) ? 3     : 2;
    gemm_tf32(A, W, bias, out, mode, As, Bs);
}

__global__ void __launch_bounds__(256) out_gemm(
    const float* __restrict__ bo, float* __restrict__ out)
{
    __shared__ uint32_t As[2 * 128 * ASTR];
    __shared__ uint32_t Bs[2 * 16 * BSTR];
    gemm_tf32(g_ctx, g_woc, bo, out, 0, As, Bs);
}

// ---------------- attention: flash 2-pass, all-ldmatrix fragments -------------
// 512 thr = 16 warps. warp = (mg = w>>2: 16 rows, kg = w&3: 32 keys/chunk).
__global__ void __launch_bounds__(512) attn_k(float* __restrict__ attn_out)
{
    extern __shared__ uint32_t smu[];
    uint32_t* qs = smu;                    // 64*QSTR  = 4352
    uint32_t* ks = qs + 64 * QSTR;         // 2*KBUF   = 17408 ([key][d])
    uint32_t* vs = ks + 2 * KBUF;          // 2*VBUF   = 16896 ([d][key])
    uint32_t* pp = vs + 2 * VBUF;          // 16*16*PPAD = 9216
    float* stm = (float*)(pp + 16 * 16 * PPAD);   // 256
    float* stl = stm + 256;                       // 256
    float* fmm = stl + 256;                       // 64
    float* fls = fmm + 64;                        // 64

    const int t    = threadIdx.x;
    const int lane = t & 31;
    const int w    = t >> 5;       // 0..15
    const int g    = lane >> 2;
    const int t4   = lane & 3;
    const int mg   = w >> 2;       // rows mg*16..+15
    const int kg   = w & 3;        // keys kg*32..+31 within chunk
    const int bh   = blockIdx.y;
    const int q0   = blockIdx.x * QROWS;

    const uint32_t smem_b = (uint32_t)__cvta_generic_to_shared(smu);
    const uint32_t qs_b = smem_b;
    const uint32_t ks_b = smem_b + 64 * QSTR * 4;
    const uint32_t vs_b = ks_b + 2 * KBUF * 4;
    const uint32_t pp_b = vs_b + 2 * VBUF * 4;

    const uint32_t* kh  = g_kh + (size_t)bh * SEQ * DK;   // [s][d]
    const uint32_t* vT  = g_vT + (size_t)bh * DK * SEQ;   // [d][s]

    // cp.async per-thread indices
    int kk_[4], kd_[4], vd_[4], vk_[4];
#pragma unroll
    for (int r = 0; r < 4; ++r) {
        int lin = r * 512 + t;
        kk_[r] = lin >> 4;  kd_[r] = (lin & 15) * 4;   // K: key, d
        vd_[r] = lin >> 5;  vk_[r] = (lin & 31) * 4;   // V: d, key
    }

    // ldmatrix per-lane address components
    const int lrow8 = (lane & 7) + ((lane >> 4) << 3);   // 0..15
    const int lc4   = ((lane >> 3) & 1) * 4;             // 0 or 4

    // stage Q
    {
        const uint32_t* qb = g_qh + ((size_t)bh * SEQ + q0) * DK;
        const int r = t >> 3, c4 = (t & 7) * 8;
        *(uint4*)&qs[r * QSTR + c4]     = *(const uint4*)&qb[r * DK + c4];
        *(uint4*)&qs[r * QSTR + c4 + 4] = *(const uint4*)&qb[r * DK + c4 + 4];
    }
    // prologue: K chunk 0 -> buf 0
#pragma unroll
    for (int r = 0; r < 4; ++r)
        cpa16(ks_b + (kk_[r] * KSTR + kd_[r]) * 4, kh + (size_t)kk_[r] * DK + kd_[r]);
    CPA_COMMIT();
    __syncthreads();

    // persistent Q A-fragments
    uint32_t afr[8][4];
    {
        const uint32_t qlane = qs_b +
            ((mg * 16 + (lane & 15)) * QSTR + (lane >> 4) * 4) * 4;
#pragma unroll
        for (int kb = 0; kb < 8; ++kb) ldsm4(afr[kb], qlane + kb * 8 * 4);
    }

    // scores B ldsm base (K key-major): rows = keys, cols = d
    const uint32_t kfrag = ks_b + ((kg * 32 + lrow8) * KSTR + lc4) * 4;
    // PV B ldsm base (V d-major): rows = d, cols = keys
    const uint32_t vfrag = vs_b + (lrow8 * VSTR + kg * 32 + lc4) * 4;

    // ============== pass 1: row stats ==============
    float mrow[2] = {-1e30f, -1e30f}, lrow[2] = {0.f, 0.f};

    for (int c = 0; c < NCH; ++c) {
        __syncthreads();
        if (c < NCH - 1) {
#pragma unroll
            for (int r = 0; r < 4; ++r)
                cpa16(ks_b + (((c + 1) & 1) * KBUF + kk_[r] * KSTR + kd_[r]) * 4,
                      kh + ((size_t)(c + 1) * CHUNK + kk_[r]) * DK + kd_[r]);
            CPA_COMMIT();
            CPA_WAIT1();
        } else {
            CPA_WAIT0();
        }
        __syncthreads();

        const uint32_t kbb = kfrag + (c & 1) * (KBUF * 4);
        float sacc[4][4];
#pragma unroll
        for (int nb = 0; nb < 4; ++nb)
#pragma unroll
            for (int i = 0; i < 4; ++i) sacc[nb][i] = 0.f;
#pragma unroll
        for (int kb = 0; kb < 8; ++kb) {
#pragma unroll
            for (int nq = 0; nq < 2; ++nq) {
                uint32_t b[4];
                ldsm4(b, kbb + (nq * 16 * KSTR + kb * 8) * 4);
                mma8(sacc[nq * 2],     afr[kb], b[0], b[1]);
                mma8(sacc[nq * 2 + 1], afr[kb], b[2], b[3]);
            }
        }
#pragma unroll
        for (int sl = 0; sl < 2; ++sl) {
            float vm = -1e30f;
#pragma unroll
            for (int nb = 0; nb < 4; ++nb)
                vm = fmaxf(vm, fmaxf(sacc[nb][sl * 2], sacc[nb][sl * 2 + 1]));
            vm = fmaxf(vm, __shfl_xor_sync(~0u, vm, 1));
            vm = fmaxf(vm, __shfl_xor_sync(~0u, vm, 2));
            const float mn = fmaxf(mrow[sl], vm);
            float cs = 0.f;
#pragma unroll
            for (int nb = 0; nb < 4; ++nb)
                cs += __expf(sacc[nb][sl * 2] - mn) + __expf(sacc[nb][sl * 2 + 1] - mn);
            cs += __shfl_xor_sync(~0u, cs, 1);
            cs += __shfl_xor_sync(~0u, cs, 2);
            lrow[sl] = lrow[sl] * __expf(mrow[sl] - mn) + cs;
            mrow[sl] = mn;
        }
    }

    // cross-key-group reduce
    if (t4 == 0) {
        stm[kg * 64 + mg * 16 + g]     = mrow[0];
        stm[kg * 64 + mg * 16 + g + 8] = mrow[1];
        stl[kg * 64 + mg * 16 + g]     = lrow[0];
        stl[kg * 64 + mg * 16 + g + 8] = lrow[1];
    }
    __syncthreads();
    if (t < 64) {
        float fm = -1e30f;
#pragma unroll
        for (int q = 0; q < 4; ++q) fm = fmaxf(fm, stm[q * 64 + t]);
        float fl = 0.f;
#pragma unroll
        for (int q = 0; q < 4; ++q) fl += stl[q * 64 + t] * __expf(stm[q * 64 + t] - fm);
        fmm[t] = fm;
        fls[t] = 1.0f / fl;
    }
    __syncthreads();
    const float fmv0 = fmm[mg * 16 + g],     flv0 = fls[mg * 16 + g];
    const float fmv1 = fmm[mg * 16 + g + 8], flv1 = fls[mg * 16 + g + 8];
    __syncthreads();

    // ============== pass 2: P write + P@V ==============
#pragma unroll
    for (int r = 0; r < 4; ++r) {
        cpa16(ks_b + (kk_[r] * KSTR + kd_[r]) * 4, kh + (size_t)kk_[r] * DK + kd_[r]);
        cpa16(vs_b + (vd_[r] * VSTR + vk_[r]) * 4, vT + (size_t)vd_[r] * SEQ + vk_[r]);
    }
    CPA_COMMIT();

    float oacc[8][4];
#pragma unroll
    for (int nb = 0; nb < 8; ++nb)
#pragma unroll
        for (int i = 0; i < 4; ++i) oacc[nb][i] = 0.f;

    float* attn_base = attn_out + ((size_t)bh * SEQ + q0) * SEQ;
    uint32_t* ppw = pp + w * 16 * PPAD;
    const uint32_t pplane = pp_b + w * 16 * PPAD * 4 +
        ((lane & 15) * PPAD + (lane >> 4) * 4) * 4;

    for (int c = 0; c < NCH; ++c) {
        __syncthreads();
        if (c < NCH - 1) {
#pragma unroll
            for (int r = 0; r < 4; ++r) {
                cpa16(ks_b + (((c + 1) & 1) * KBUF + kk_[r] * KSTR + kd_[r]) * 4,
                      kh + ((size_t)(c + 1) * CHUNK + kk_[r]) * DK + kd_[r]);
                cpa16(vs_b + (((c + 1) & 1) * VBUF + vd_[r] * VSTR + vk_[r]) * 4,
                      vT + (size_t)vd_[r] * SEQ + (c + 1) * CHUNK + vk_[r]);
            }
            CPA_COMMIT();
            CPA_WAIT1();
        } else {
            CPA_WAIT0();
        }
        __syncthreads();

        // scores
        const uint32_t kbb = kfrag + (c & 1) * (KBUF * 4);
        float sacc[4][4];
#pragma unroll
        for (int nb = 0; nb < 4; ++nb)
#pragma unroll
            for (int i = 0; i < 4; ++i) sacc[nb][i] = 0.f;
#pragma unroll
        for (int kb = 0; kb < 8; ++kb) {
#pragma unroll
            for (int nq = 0; nq < 2; ++nq) {
                uint32_t b[4];
                ldsm4(b, kbb + (nq * 16 * KSTR + kb * 8) * 4);
                mma8(sacc[nq * 2],     afr[kb], b[0], b[1]);
                mma8(sacc[nq * 2 + 1], afr[kb], b[2], b[3]);
            }
        }
        // p = exp(s - m) * invl: gmem write + tf32 patch
#pragma unroll
        for (int nb = 0; nb < 4; ++nb) {
            const float p00 = __expf(sacc[nb][0] - fmv0) * flv0;
            const float p01 = __expf(sacc[nb][1] - fmv0) * flv0;
            const float p10 = __expf(sacc[nb][2] - fmv1) * flv1;
            const float p11 = __expf(sacc[nb][3] - fmv1) * flv1;
            const int pc = nb * 8 + 2 * t4;
            *(uint2*)&ppw[g * PPAD + pc]       = make_uint2(f2tf(p00), f2tf(p01));
            *(uint2*)&ppw[(g + 8) * PPAD + pc] = make_uint2(f2tf(p10), f2tf(p11));
            const int col = c * CHUNK + kg * 32 + pc;
            __stcs((float2*)&attn_base[(size_t)(mg * 16 + g) * SEQ + col],
                   make_float2(p00, p01));
            __stcs((float2*)&attn_base[(size_t)(mg * 16 + g + 8) * SEQ + col],
                   make_float2(p10, p11));
        }
        __syncwarp();

        // P @ V: A = own 16x32 P patch (4 frags), B = V via ldsm
        const uint32_t vbb = vfrag + (c & 1) * (VBUF * 4);
#pragma unroll
        for (int kb2 = 0; kb2 < 4; ++kb2) {
            uint32_t a[4];
            ldsm4(a, pplane + kb2 * 8 * 4);
#pragma unroll
            for (int np = 0; np < 4; ++np) {
                uint32_t b[4];
                ldsm4(b, vbb + (np * 16 * VSTR + kb2 * 8) * 4);
                mma8(oacc[np * 2],     a, b[0], b[1]);
                mma8(oacc[np * 2 + 1], a, b[2], b[3]);
            }
        }
    }

    // ---- O reduce across 4 key-group warps per m-group ----
    __syncthreads();
    float* osm = (float*)ks;   // 16 warps x [16][68] = 17408 floats
#pragma unroll
    for (int nb = 0; nb < 8; ++nb) {
        const int oc = nb * 8 + 2 * t4;
        *(float2*)&osm[w * 1088 + g * 68 + oc]       = make_float2(oacc[nb][0], oacc[nb][1]);
        *(float2*)&osm[w * 1088 + (g + 8) * 68 + oc] = make_float2(oacc[nb][2], oacc[nb][3]);
    }
    __syncthreads();
    const int b = bh >> 4, h = bh & 15;
#pragma unroll
    for (int i = t; i < 4096; i += 512) {
        const int rr = i >> 6, d = i & 63;
        const int mg2 = rr >> 4, r16 = rr & 15;
        float s = 0.f;
#pragma unroll
        for (int q = 0; q < 4; ++q)
            s += osm[(mg2 * 4 + q) * 1088 + r16 * 68 + d];
        g_ctx[((size_t)b * SEQ + q0 + rr) * D_MODEL + h * DK + d] = f2tf(s);
    }
}

// ---------------- launch -----------------------------------------------------
extern "C" void kernel_launch(void* const* d_in, const int* in_sizes, int n_in,
                              void* d_out, int out_size)
{
    (void)in_sizes; (void)n_in; (void)out_size;
    const float* q  = (const float*)d_in[0];
    const float* k  = (const float*)d_in[1];
    const float* v  = (const float*)d_in[2];
    const float* wq = (const float*)d_in[3];
    const float* bq = (const float*)d_in[4];
    const float* wk = (const float*)d_in[5];
    const float* bk = (const float*)d_in[6];
    const float* wv = (const float*)d_in[7];
    const float* bv = (const float*)d_in[8];
    const float* wo = (const float*)d_in[9];
    const float* bo = (const float*)d_in[10];

    float* out  = (float*)d_out;                       // [B,S,D]
    float* attn = out + (size_t)MROWS * D_MODEL;       // [B,H,S,S]

    const int smem = (64 * QSTR + 2 * KBUF + 2 * VBUF + 16 * 16 * PPAD + 640) * 4;
    cudaFuncSetAttribute(attn_k, cudaFuncAttributeMaxDynamicSharedMemorySize, smem);

    cvt_inputs <<<dim3(MROWS * D_MODEL / (256 * 4), 3), 256>>>(q, k, v);
    cvt_weights<<<dim3(D_MODEL * D_MODEL / (256 * 4), 4), 256>>>(wq, wk, wv, wo);
    qkv_gemm_p<<<dim3(8, 32, 3), 256>>>(bq, bk, bv);
    attn_k<<<dim3(SEQ / QROWS, NBH), 512, smem>>>(attn);
    out_gemm<<<dim3(8, 32), 256>>>(bo, out);
}